// round 6
// baseline (speedup 1.0000x reference)
#include <cuda_runtime.h>
#include <cstdint>

// Problem constants (fixed by dataset setup_inputs)
#define NE 400000          // edges
#define NH 8               // heads
#define ND 32              // head dim
#define MAX_NODES 50000    // n_nodes
#define SEG (MAX_NODES * NH)
#define C 256              // edges per block (= blockDim.x)

// Scratch (allocation-free rule: __device__ globals). Only boundary edges
// (~5% of all edges) ever touch these.
__device__ float g_score[NE * NH];  // exp scores for boundary edges
__device__ float g_sum[SEG];        // global sums for boundary segments

// ---------------------------------------------------------------------------
// Fused kernel: block b owns edges [b*C, b*C+C).
//  Phase 1: warp-per-edge coalesced score + exp -> smem.
//  Phase 2: per-segment-slice sums in smem. EVERY chunk treats local pos 0 as
//           a slice start (fix for segments continuing across chunks): each
//           chunk owns a contiguous slice of each segment and sums it locally.
//  Phase 3: interior segments (entirely within the chunk) divide + write out.
//           boundary slices spill exp to g_score, atomicAdd slice sums into
//           g_sum; fixup kernel finishes them with the complete global sum.
//  Barriers: all __syncthreads() are convergent (outside validity branches).
// ---------------------------------------------------------------------------
__global__ void __launch_bounds__(256) fused_kernel(
    const float* __restrict__ q,
    const float* __restrict__ k,
    const float* __restrict__ attn,
    const int*   __restrict__ index,
    float* __restrict__ out)
{
    __shared__ float4 s_attn[2 * NH * 8];                // 2 KB
    __shared__ __align__(16) float s_sc[C][NH];          // 8 KB exp scores
    __shared__ __align__(16) float s_sum[C][NH];         // 8 KB slice sums
    __shared__ int s_idx[C + 2];  // s_idx[j+1] = index[s+j]; [0]=prev, [C+1]=next

    const int tid = threadIdx.x;
    const int s   = blockIdx.x * C;

    // attn to smem: s_attn[h*8+r] = a_q[h][4r..], +64 = a_k.
    {
        const float4* a4 = (const float4*)attn;
        for (int i = tid; i < NH * 16; i += 256) {
            int h = i >> 4, j = i & 15;
            if (j < 8) s_attn[h * 8 + j] = a4[i];
            else       s_attn[64 + h * 8 + (j - 8)] = a4[i];
        }
    }
    // index slice (+ neighbors for boundary detection)
    {
        int e = s + tid;
        s_idx[tid + 1] = (e < NE) ? index[e] : (-2 - tid);  // distinct sentinels
        if (tid == 0) s_idx[0]     = (s > 0)      ? index[s - 1] : -1;
        if (tid == 1) s_idx[C + 1] = (s + C < NE) ? index[s + C] : -1;
    }
    __syncthreads();

    // ---------------- Phase 1: scores ----------------
    const int lane = tid & 31;
    const int w    = tid >> 5;        // warp 0..7, owns local edges [w*32, w*32+32)
    const int g    = lane >> 3;       // head group (heads g and g+4)
    const int r    = lane & 7;        // quad within head

    const float4 aq0 = s_attn[g * 8 + r];
    const float4 aq1 = s_attn[(g + 4) * 8 + r];
    const float4 ak0 = s_attn[64 + g * 8 + r];
    const float4 ak1 = s_attn[64 + (g + 4) * 8 + r];

#pragma unroll 2
    for (int i = 0; i < 32; i++) {
        int le = w * 32 + i;
        int e  = s + le;
        if (e >= NE) break;   // uniform across the warp; no barriers inside

        const float4* __restrict__ q4 = (const float4*)q + (size_t)e * 64;
        const float4* __restrict__ k4 = (const float4*)k + (size_t)e * 64;
        float4 qa = q4[lane];
        float4 qb = q4[32 + lane];
        float4 ka = k4[lane];
        float4 kb = k4[32 + lane];

        float acc0 = qa.x * aq0.x;
        acc0 = fmaf(qa.y, aq0.y, acc0);
        acc0 = fmaf(qa.z, aq0.z, acc0);
        acc0 = fmaf(qa.w, aq0.w, acc0);
        acc0 = fmaf(ka.x, ak0.x, acc0);
        acc0 = fmaf(ka.y, ak0.y, acc0);
        acc0 = fmaf(ka.z, ak0.z, acc0);
        acc0 = fmaf(ka.w, ak0.w, acc0);

        float acc1 = qb.x * aq1.x;
        acc1 = fmaf(qb.y, aq1.y, acc1);
        acc1 = fmaf(qb.z, aq1.z, acc1);
        acc1 = fmaf(qb.w, aq1.w, acc1);
        acc1 = fmaf(kb.x, ak1.x, acc1);
        acc1 = fmaf(kb.y, ak1.y, acc1);
        acc1 = fmaf(kb.z, ak1.z, acc1);
        acc1 = fmaf(kb.w, ak1.w, acc1);

#pragma unroll
        for (int o = 4; o >= 1; o >>= 1) {
            acc0 += __shfl_xor_sync(0xFFFFFFFFu, acc0, o);
            acc1 += __shfl_xor_sync(0xFFFFFFFFu, acc1, o);
        }

        float e0 = __expf(fmaxf(acc0, 0.0f));   // head g   (valid on leaders)
        float e1 = __expf(fmaxf(acc1, 0.0f));   // head g+4 (valid on leaders)

        int src = (lane & 3) * 8;
        float vlo = __shfl_sync(0xFFFFFFFFu, e0, src);
        float vhi = __shfl_sync(0xFFFFFFFFu, e1, src);

        if (lane < 4)                    s_sc[le][lane]           = vlo;
        else if (lane >= 8 && lane < 12) s_sc[le][(lane - 8) + 4] = vhi;
    }
    __syncthreads();

    // ---------------- Phase 2: segment-slice sums ----------------
    const int t = tid;
    const int e = s + t;
    const bool valid = (e < NE);
    const int  n     = s_idx[t + 1];              // sentinel if !valid
    // FIX: local pos 0 is always a slice start, even if the segment continues
    // from the previous chunk — that slice's sum must still be accumulated.
    const bool isStart = valid && (t == 0 || s_idx[t] != n);
    const bool bnd     = valid && ((s_idx[0] == n) || (s_idx[C + 1] == n));

    if (isStart) {
        float4 a = make_float4(0.f, 0.f, 0.f, 0.f);
        float4 b = make_float4(0.f, 0.f, 0.f, 0.f);
        int j = t;
        while (j < C && s_idx[j + 1] == n) {
            float4 x = *(const float4*)&s_sc[j][0];
            float4 y = *(const float4*)&s_sc[j][4];
            a.x += x.x; a.y += x.y; a.z += x.z; a.w += x.w;
            b.x += y.x; b.y += y.y; b.z += y.z; b.w += y.w;
            j++;
        }
        *(float4*)&s_sum[t][0] = a;
        *(float4*)&s_sum[t][4] = b;
        if (bnd) {
            float* gs = &g_sum[n * NH];
            atomicAdd(gs + 0, a.x); atomicAdd(gs + 1, a.y);
            atomicAdd(gs + 2, a.z); atomicAdd(gs + 3, a.w);
            atomicAdd(gs + 4, b.x); atomicAdd(gs + 5, b.y);
            atomicAdd(gs + 6, b.z); atomicAdd(gs + 7, b.w);
        }
    }
    __syncthreads();   // single convergent barrier

    // ---------------- Phase 3: output (predicated, no barriers) ----------
    if (valid) {
        float4 x = *(const float4*)&s_sc[t][0];
        float4 y = *(const float4*)&s_sc[t][4];
        if (bnd) {
            // spill; fixup kernel normalizes with the complete global sum
            float4* gp = (float4*)g_score + (size_t)e * 2;
            gp[0] = x; gp[1] = y;
        } else {
            // locate my segment start (interior => never crosses local 0 as
            // a continuation, since that case is bnd)
            int st = t;
            while (st > 0 && s_idx[st] == n) st--;
            float4 da = *(const float4*)&s_sum[st][0];
            float4 db = *(const float4*)&s_sum[st][4];
            float4 o0, o1;
            o0.x = x.x / da.x; o0.y = x.y / da.y; o0.z = x.z / da.z; o0.w = x.w / da.w;
            o1.x = y.x / db.x; o1.y = y.y / db.y; o1.z = y.z / db.z; o1.w = y.w / db.w;
            float4* op = (float4*)out + (size_t)e * 2;
            op[0] = o0; op[1] = o1;
        }
    }
}

// ---------------------------------------------------------------------------
// Fixup: normalize boundary edges (same chunking => same boundary predicate).
// ---------------------------------------------------------------------------
__global__ void __launch_bounds__(256) fixup_kernel(
    const int* __restrict__ index,
    float* __restrict__ out)
{
    int e = blockIdx.x * C + threadIdx.x;
    if (e >= NE) return;
    int s = blockIdx.x * C;
    int n = index[e];
    bool bnd = (s > 0 && index[s - 1] == n) || (s + C < NE && index[s + C] == n);
    if (!bnd) return;

    const float4* sp = (const float4*)g_score + (size_t)e * 2;
    const float4* dp = (const float4*)(g_sum + (size_t)n * NH);
    float4 x = sp[0], y = sp[1];
    float4 da = dp[0], db = dp[1];
    float4 o0, o1;
    o0.x = x.x / da.x; o0.y = x.y / da.y; o0.z = x.z / da.z; o0.w = x.w / da.w;
    o1.x = y.x / db.x; o1.y = y.y / db.y; o1.z = y.z / db.z; o1.w = y.w / db.w;
    float4* op = (float4*)out + (size_t)e * 2;
    op[0] = o0; op[1] = o1;
}

// ---------------------------------------------------------------------------
extern "C" void kernel_launch(void* const* d_in, const int* in_sizes, int n_in,
                              void* d_out, int out_size)
{
    const float* q     = (const float*)d_in[0];
    const float* k     = (const float*)d_in[1];
    const float* attn  = (const float*)d_in[2];
    const int*   index = (const int*)d_in[3];
    float* out = (float*)d_out;

    (void)in_sizes; (void)n_in; (void)out_size;

    // Zero boundary-segment sums (graph memset node).
    void* sum_ptr = nullptr;
    cudaGetSymbolAddress(&sum_ptr, g_sum);
    cudaMemsetAsync(sum_ptr, 0, (size_t)SEG * sizeof(float));

    const int nblk = (NE + C - 1) / C;   // 1563
    fused_kernel<<<nblk, 256>>>(q, k, attn, index, out);
    fixup_kernel<<<nblk, 256>>>(index, out);
}